// round 4
// baseline (speedup 1.0000x reference)
#include <cuda_runtime.h>
#include <math.h>

#define NN   50000
#define EE   100000
#define GG   2048
#define DD   32

typedef unsigned long long ull;

// ---------------- device scratch ----------------
__device__ float g_h[NN * DD];
__device__ float g_aggr[NN * DD];
__device__ float g_Y[NN * 5 * DD];
__device__ float g_pool[GG * DD];
__device__ float g_cnt[GG];

// packed weights (16B chunks of 4 input-dims, pair-major for f32x2)
__device__ __align__(16) float P_RW[1024];   // root_w: [(i4*32+o)*4 + (i&3)]
__device__ __align__(16) float P_WG[6144];   // fused GRU: [((d4*3+g)*32+lane)*4 + (d&3)]
__device__ __align__(16) float P_MS[5120];   // 5 msg mats: [((i4*5+j)*32+lane)*4 + (i&3)]

// ---------------- f32x2 helpers ----------------
__device__ __forceinline__ ull ffma2(ull a, ull b, ull c) {
    ull d;
    asm("fma.rn.f32x2 %0, %1, %2, %3;" : "=l"(d) : "l"(a), "l"(b), "l"(c));
    return d;
}
__device__ __forceinline__ float flo(ull v) { return __uint_as_float((unsigned)v); }
__device__ __forceinline__ float fhi(ull v) { return __uint_as_float((unsigned)(v >> 32)); }
__device__ __forceinline__ float psum(ull v) { return flo(v) + fhi(v); }

// ---------------- K_pack: zero pool + build packed weights ----------------
__global__ void k_pack(const float* __restrict__ root_w,
                       const float* __restrict__ wi,
                       const float* __restrict__ wh,
                       const float* __restrict__ nn_w,
                       const float* __restrict__ nn_b) {
    int gid = blockIdx.x * blockDim.x + threadIdx.x;
    if (gid < GG * DD) g_pool[gid] = 0.0f;
    if (gid < GG) g_cnt[gid] = 0.0f;

    if (gid < 1024) {                        // root_w [i*32+o] -> P_RW
        int pos = gid & 3, o = (gid >> 2) & 31, i4 = gid >> 7;
        P_RW[gid] = root_w[(i4 * 4 + pos) * 32 + o];
    } else if (gid < 1024 + 6144) {          // fused GRU weights
        int t2 = gid - 1024;
        int pos = t2 & 3;
        int tmp = t2 >> 2;
        int lane = tmp & 31;
        int gk = (tmp >> 5) % 3;
        int d4 = (tmp >> 5) / 3;
        int d = d4 * 4 + pos;
        int k = gk * 32 + lane;
        P_WG[t2] = (d < 32) ? wi[k * 32 + d] : wh[k * 32 + (d - 32)];
    } else if (gid < 7168 + 5120) {          // 5 message matrices
        int t2 = gid - 7168;
        int pos = t2 & 3;
        int tmp = t2 >> 2;
        int lane = tmp & 31;
        int j = (tmp >> 5) % 5;
        int i4 = (tmp >> 5) / 5;
        int i = i4 * 4 + pos;
        P_MS[t2] = (j < 4) ? nn_w[(i * 32 + lane) * 4 + j] : nn_b[i * 32 + lane];
    }
}

// ---------------- K_init: h0 = relu(lin0); Y0 = h0 @ M_j ; zero aggr ----------------
// 8 warps, 8 nodes/warp -> 64 nodes/block
__global__ __launch_bounds__(256) void k_init(const float* __restrict__ x,
                                              const float* __restrict__ w,   // [32,11]
                                              const float* __restrict__ b) { // [32]
    __shared__ __align__(16) float hsm[8][8][32];
    int t = threadIdx.x, wrp = t >> 5, lane = t & 31;
    int n0 = blockIdx.x * 64 + wrp * 8;
    float (*row)[32] = hsm[wrp];

    float bias = __ldg(&b[lane]);
    float wv[11];
#pragma unroll
    for (int f = 0; f < 11; f++) wv[f] = __ldg(&w[lane * 11 + f]);

    float hn[8];
#pragma unroll
    for (int n = 0; n < 8; n++) {
        int node = n0 + n;
        float s = bias;
        if (node < NN) {
#pragma unroll
            for (int f = 0; f < 11; f++) s += __ldg(&x[node * 11 + f]) * wv[f];
        }
        hn[n] = fmaxf(s, 0.0f);
        row[n][lane] = hn[n];
    }
    __syncwarp();

    ull y[8][5];
#pragma unroll
    for (int n = 0; n < 8; n++)
#pragma unroll
        for (int j = 0; j < 5; j++) y[n][j] = 0ull;

#pragma unroll
    for (int i4 = 0; i4 < 8; i4++) {
        ulonglong2 mw[5];
#pragma unroll
        for (int j = 0; j < 5; j++)
            mw[j] = *(const ulonglong2*)&P_MS[((i4 * 5 + j) * 32 + lane) * 4];
#pragma unroll
        for (int n = 0; n < 8; n++) {
            ulonglong2 h2 = *(const ulonglong2*)&row[n][i4 * 4];
#pragma unroll
            for (int j = 0; j < 5; j++) {
                y[n][j] = ffma2(h2.x, mw[j].x, y[n][j]);
                y[n][j] = ffma2(h2.y, mw[j].y, y[n][j]);
            }
        }
    }
#pragma unroll
    for (int n = 0; n < 8; n++) {
        int node = n0 + n;
        if (node >= NN) break;
        g_h[node * 32 + lane] = hn[n];
        g_aggr[node * 32 + lane] = 0.0f;
        float* yb = &g_Y[(size_t)node * 160];
#pragma unroll
        for (int j = 0; j < 5; j++) yb[j * 32 + lane] = psum(y[n][j]);
    }
}

// ---------------- K_edge: per-edge message + scatter-add ----------------
__global__ void k_edge(const int* __restrict__ ei,        // [2,E]
                       const float* __restrict__ ea) {    // [E,4]
    int gt   = blockIdx.x * blockDim.x + threadIdx.x;
    int e    = gt >> 5;
    int lane = gt & 31;
    if (e >= EE) return;
    int s = __ldg(&ei[e]);
    int d = __ldg(&ei[EE + e]);
    float4 a = __ldg(&reinterpret_cast<const float4*>(ea)[e]);
    const float* yb = &g_Y[(size_t)s * 160];
    float msg = __ldg(&yb[4 * 32 + lane])
              + a.x * __ldg(&yb[0 * 32 + lane])
              + a.y * __ldg(&yb[1 * 32 + lane])
              + a.z * __ldg(&yb[2 * 32 + lane])
              + a.w * __ldg(&yb[3 * 32 + lane]);
    atomicAdd(&g_aggr[d * 32 + lane], msg);
}

// ---------------- K_node: NNConv-root + fused GRU + next-round Y (or pooling) ----------------
// 8 warps, 8 nodes/warp. mh[n][0..31]=m (later hn), mh[n][32..63]=h
__global__ __launch_bounds__(256) void k_node(const float* __restrict__ conv_b, // [32]
                                              const float* __restrict__ bi,     // [96]
                                              const float* __restrict__ bh,     // [96]
                                              const int* __restrict__ batch,
                                              int last) {
    __shared__ __align__(16) float mh[8][8][64];
    int t = threadIdx.x, wrp = t >> 5, lane = t & 31;
    int n0 = blockIdx.x * 64 + wrp * 8;
    float (*row)[64] = mh[wrp];

    // stage h
#pragma unroll
    for (int n = 0; n < 8; n++) {
        int node = n0 + n;
        row[n][32 + lane] = (node < NN) ? g_h[node * 32 + lane] : 0.0f;
    }
    __syncwarp();

    // --- root mat-vec ---
    ull acc[8];
#pragma unroll
    for (int n = 0; n < 8; n++) acc[n] = 0ull;
#pragma unroll
    for (int i4 = 0; i4 < 8; i4++) {
        ulonglong2 wv = *(const ulonglong2*)&P_RW[(i4 * 32 + lane) * 4];
#pragma unroll
        for (int n = 0; n < 8; n++) {
            ulonglong2 h2 = *(const ulonglong2*)&row[n][32 + i4 * 4];
            acc[n] = ffma2(h2.x, wv.x, acc[n]);
            acc[n] = ffma2(h2.y, wv.y, acc[n]);
        }
    }
    float cb = __ldg(&conv_b[lane]);
#pragma unroll
    for (int n = 0; n < 8; n++) {
        int node = n0 + n;
        float a = 0.0f;
        if (node < NN) {
            a = g_aggr[node * 32 + lane];
            g_aggr[node * 32 + lane] = 0.0f;   // pre-zero for next round
        }
        row[n][lane] = fmaxf(psum(acc[n]) + a + cb, 0.0f);
    }
    __syncwarp();

    // --- fused GRU gates over 64-dim [m;h] ---
    ull A[8], B[8], C[8], D[8];
#pragma unroll
    for (int n = 0; n < 8; n++) { A[n] = B[n] = C[n] = D[n] = 0ull; }
#pragma unroll
    for (int d4 = 0; d4 < 16; d4++) {
        ulonglong2 wr = *(const ulonglong2*)&P_WG[((d4 * 3 + 0) * 32 + lane) * 4];
        ulonglong2 wz = *(const ulonglong2*)&P_WG[((d4 * 3 + 1) * 32 + lane) * 4];
        ulonglong2 wn = *(const ulonglong2*)&P_WG[((d4 * 3 + 2) * 32 + lane) * 4];
#pragma unroll
        for (int n = 0; n < 8; n++) {
            ulonglong2 v = *(const ulonglong2*)&row[n][d4 * 4];
            A[n] = ffma2(v.x, wr.x, A[n]);
            A[n] = ffma2(v.y, wr.y, A[n]);
            B[n] = ffma2(v.x, wz.x, B[n]);
            B[n] = ffma2(v.y, wz.y, B[n]);
            if (d4 < 8) {           // m-part -> inn
                C[n] = ffma2(v.x, wn.x, C[n]);
                C[n] = ffma2(v.y, wn.y, C[n]);
            } else {                // h-part -> hn
                D[n] = ffma2(v.x, wn.x, D[n]);
                D[n] = ffma2(v.y, wn.y, D[n]);
            }
        }
    }
    float bir = __ldg(&bi[lane]), biz = __ldg(&bi[lane + 32]), bin = __ldg(&bi[lane + 64]);
    float bhr = __ldg(&bh[lane]), bhz = __ldg(&bh[lane + 32]), bhn = __ldg(&bh[lane + 64]);

    float hn[8];
#pragma unroll
    for (int n = 0; n < 8; n++) {
        float h  = row[n][32 + lane];
        float ra = psum(A[n]) + bir + bhr;
        float za = psum(B[n]) + biz + bhz;
        float cn = psum(C[n]) + bin;
        float dn = psum(D[n]) + bhn;
        float r  = 1.0f / (1.0f + __expf(-ra));
        float z  = 1.0f / (1.0f + __expf(-za));
        float nv = tanhf(cn + r * dn);
        hn[n] = (1.0f - z) * nv + z * h;
    }

    if (last) {
#pragma unroll
        for (int n = 0; n < 8; n++) {
            int node = n0 + n;
            if (node >= NN) break;
            int bg = __ldg(&batch[node]);
            atomicAdd(&g_pool[bg * 32 + lane], hn[n]);
            if (lane == 0) atomicAdd(&g_cnt[bg], 1.0f);
        }
        return;
    }

    // --- fused Y for next round ---
#pragma unroll
    for (int n = 0; n < 8; n++) row[n][lane] = hn[n];
    __syncwarp();

    ull y[8][5];
#pragma unroll
    for (int n = 0; n < 8; n++)
#pragma unroll
        for (int j = 0; j < 5; j++) y[n][j] = 0ull;
#pragma unroll
    for (int i4 = 0; i4 < 8; i4++) {
        ulonglong2 mw[5];
#pragma unroll
        for (int j = 0; j < 5; j++)
            mw[j] = *(const ulonglong2*)&P_MS[((i4 * 5 + j) * 32 + lane) * 4];
#pragma unroll
        for (int n = 0; n < 8; n++) {
            ulonglong2 h2 = *(const ulonglong2*)&row[n][i4 * 4];
#pragma unroll
            for (int j = 0; j < 5; j++) {
                y[n][j] = ffma2(h2.x, mw[j].x, y[n][j]);
                y[n][j] = ffma2(h2.y, mw[j].y, y[n][j]);
            }
        }
    }
#pragma unroll
    for (int n = 0; n < 8; n++) {
        int node = n0 + n;
        if (node >= NN) break;
        g_h[node * 32 + lane] = hn[n];
        float* yb = &g_Y[(size_t)node * 160];
#pragma unroll
        for (int j = 0; j < 5; j++) yb[j * 32 + lane] = psum(y[n][j]);
    }
}

// ---------------- K_final: logits + log_softmax ----------------
__global__ void k_final(const float* __restrict__ w,   // [2,32]
                        const float* __restrict__ b,   // [2]
                        float* __restrict__ out) {     // [G,2]
    int g = blockIdx.x * blockDim.x + threadIdx.x;
    if (g >= GG) return;
    float inv = 1.0f / fmaxf(g_cnt[g], 1.0f);
    float l0 = b[0], l1 = b[1];
#pragma unroll
    for (int d = 0; d < DD; d++) {
        float p = g_pool[g * DD + d] * inv;
        l0 += p * w[d];
        l1 += p * w[DD + d];
    }
    float mx  = fmaxf(l0, l1);
    float lse = mx + logf(__expf(l0 - mx) + __expf(l1 - mx));
    out[g * 2 + 0] = l0 - lse;
    out[g * 2 + 1] = l1 - lse;
}

// ---------------- launch ----------------
extern "C" void kernel_launch(void* const* d_in, const int* in_sizes, int n_in,
                              void* d_out, int out_size) {
    const float* x        = (const float*)d_in[0];
    const float* edge_attr= (const float*)d_in[1];
    const float* lin0_w   = (const float*)d_in[2];
    const float* lin0_b   = (const float*)d_in[3];
    const float* nn_w     = (const float*)d_in[4];
    const float* nn_b     = (const float*)d_in[5];
    const float* root_w   = (const float*)d_in[6];
    const float* conv_b   = (const float*)d_in[7];
    const float* gru_wi   = (const float*)d_in[8];
    const float* gru_wh   = (const float*)d_in[9];
    const float* gru_bi   = (const float*)d_in[10];
    const float* gru_bh   = (const float*)d_in[11];
    const float* lin1_w   = (const float*)d_in[12];
    const float* lin1_b   = (const float*)d_in[13];
    const int*   edge_idx = (const int*)d_in[14];
    const int*   batch    = (const int*)d_in[15];
    float* out = (float*)d_out;

    const int TPB = 256;
    const int nodeBlocks = (NN + 63) / 64;                 // 782
    const int edgeWarpBlocks = (EE * 32 + TPB - 1) / TPB;  // 12500
    const int packBlocks = (GG * DD + TPB - 1) / TPB;      // 256

    k_pack<<<packBlocks, TPB>>>(root_w, gru_wi, gru_wh, nn_w, nn_b);
    k_init<<<nodeBlocks, TPB>>>(x, lin0_w, lin0_b);

    for (int round = 0; round < 3; round++) {
        k_edge<<<edgeWarpBlocks, TPB>>>(edge_idx, edge_attr);
        k_node<<<nodeBlocks, TPB>>>(conv_b, gru_bi, gru_bh, batch, round == 2);
    }

    k_final<<<(GG + TPB - 1) / TPB, TPB>>>(lin1_w, lin1_b, out);
}

// round 5
// speedup vs baseline: 1.2401x; 1.2401x over previous
#include <cuda_runtime.h>
#include <math.h>

#define NN   50000
#define EE   100000
#define GG   2048
#define DD   32

typedef unsigned long long ull;

// ---------------- device scratch ----------------
__device__ float g_h[NN * DD];
__device__ float g_aggr[NN * DD];
__device__ float g_Y[NN * 5 * DD];
__device__ float g_pool[GG * DD];
__device__ float g_cnt[GG];

// packed weights (16B chunks of 4 input-dims)
__device__ __align__(16) float P_RW[1024];   // root_w: [(i4*32+o)*4 + (i&3)]
__device__ __align__(16) float P_WG[6144];   // fused GRU: [((d4*3+g)*32+lane)*4 + (d&3)]
__device__ __align__(16) float P_MS[5120];   // 5 msg mats: [((i4*5+j)*32+lane)*4 + (i&3)]

// ---------------- f32x2 helpers ----------------
__device__ __forceinline__ ull ffma2(ull a, ull b, ull c) {
    ull d;
    asm("fma.rn.f32x2 %0, %1, %2, %3;" : "=l"(d) : "l"(a), "l"(b), "l"(c));
    return d;
}
__device__ __forceinline__ float flo(ull v) { return __uint_as_float((unsigned)v); }
__device__ __forceinline__ float fhi(ull v) { return __uint_as_float((unsigned)(v >> 32)); }
__device__ __forceinline__ float psum(ull v) { return flo(v) + fhi(v); }

// ---------------- K_pack: zero pool + build packed weights ----------------
__global__ void k_pack(const float* __restrict__ root_w,
                       const float* __restrict__ wi,
                       const float* __restrict__ wh,
                       const float* __restrict__ nn_w,
                       const float* __restrict__ nn_b) {
    int gid = blockIdx.x * blockDim.x + threadIdx.x;
    if (gid < GG * DD) g_pool[gid] = 0.0f;
    if (gid < GG) g_cnt[gid] = 0.0f;

    if (gid < 1024) {                        // root_w [i*32+o] -> P_RW
        int pos = gid & 3, o = (gid >> 2) & 31, i4 = gid >> 7;
        P_RW[gid] = root_w[(i4 * 4 + pos) * 32 + o];
    } else if (gid < 1024 + 6144) {          // fused GRU weights
        int t2 = gid - 1024;
        int pos = t2 & 3;
        int tmp = t2 >> 2;
        int lane = tmp & 31;
        int gk = (tmp >> 5) % 3;
        int d4 = (tmp >> 5) / 3;
        int d = d4 * 4 + pos;
        int k = gk * 32 + lane;
        P_WG[t2] = (d < 32) ? wi[k * 32 + d] : wh[k * 32 + (d - 32)];
    } else if (gid < 7168 + 5120) {          // 5 message matrices
        int t2 = gid - 7168;
        int pos = t2 & 3;
        int tmp = t2 >> 2;
        int lane = tmp & 31;
        int j = (tmp >> 5) % 5;
        int i4 = (tmp >> 5) / 5;
        int i = i4 * 4 + pos;
        P_MS[t2] = (j < 4) ? nn_w[(i * 32 + lane) * 4 + j] : nn_b[i * 32 + lane];
    }
}

// ---------------- K_init: h0 = relu(lin0); Y0 = h0 @ M_j ; zero aggr ----------------
// 8 warps, 8 nodes/warp -> 64 nodes/block
__global__ __launch_bounds__(256, 2) void k_init(const float* __restrict__ x,
                                                 const float* __restrict__ w,   // [32,11]
                                                 const float* __restrict__ b) { // [32]
    __shared__ __align__(16) float hsm[8][8][32];
    int t = threadIdx.x, wrp = t >> 5, lane = t & 31;
    int n0 = blockIdx.x * 64 + wrp * 8;
    float (*row)[32] = hsm[wrp];

    float bias = __ldg(&b[lane]);
    float wv[11];
#pragma unroll
    for (int f = 0; f < 11; f++) wv[f] = __ldg(&w[lane * 11 + f]);

    float hn[8];
#pragma unroll
    for (int n = 0; n < 8; n++) {
        int node = n0 + n;
        float s = bias;
        if (node < NN) {
#pragma unroll
            for (int f = 0; f < 11; f++) s += __ldg(&x[node * 11 + f]) * wv[f];
        }
        hn[n] = fmaxf(s, 0.0f);
        row[n][lane] = hn[n];
    }
    __syncwarp();

    ull y[8][5];
#pragma unroll
    for (int n = 0; n < 8; n++)
#pragma unroll
        for (int j = 0; j < 5; j++) y[n][j] = 0ull;

#pragma unroll
    for (int i4 = 0; i4 < 8; i4++) {
        ulonglong2 mw[5];
#pragma unroll
        for (int j = 0; j < 5; j++)
            mw[j] = *(const ulonglong2*)&P_MS[((i4 * 5 + j) * 32 + lane) * 4];
#pragma unroll
        for (int n = 0; n < 8; n++) {
            ulonglong2 h2 = *(const ulonglong2*)&row[n][i4 * 4];
#pragma unroll
            for (int j = 0; j < 5; j++) {
                y[n][j] = ffma2(h2.x, mw[j].x, y[n][j]);
                y[n][j] = ffma2(h2.y, mw[j].y, y[n][j]);
            }
        }
    }
#pragma unroll
    for (int n = 0; n < 8; n++) {
        int node = n0 + n;
        if (node >= NN) break;
        g_h[node * 32 + lane] = hn[n];
        g_aggr[node * 32 + lane] = 0.0f;
        float* yb = &g_Y[(size_t)node * 160];
#pragma unroll
        for (int j = 0; j < 5; j++) yb[j * 32 + lane] = psum(y[n][j]);
    }
}

// ---------------- K_edge: 2 edges per warp, batched gathers + scatter-add ----------------
__global__ void k_edge(const int* __restrict__ ei,        // [2,E]
                       const float* __restrict__ ea) {    // [E,4]
    int gt   = blockIdx.x * blockDim.x + threadIdx.x;
    int wrp  = gt >> 5;
    int lane = gt & 31;
    int e0   = wrp * 2;
    if (e0 >= EE) return;

    int s0 = __ldg(&ei[e0]);
    int d0 = __ldg(&ei[EE + e0]);
    float4 a0 = __ldg(&reinterpret_cast<const float4*>(ea)[e0]);
    const float* yb0 = &g_Y[(size_t)s0 * 160];

    bool has1 = (e0 + 1) < EE;
    int s1 = has1 ? __ldg(&ei[e0 + 1]) : s0;
    int d1 = has1 ? __ldg(&ei[EE + e0 + 1]) : d0;
    float4 a1 = has1 ? __ldg(&reinterpret_cast<const float4*>(ea)[e0 + 1]) : a0;
    const float* yb1 = &g_Y[(size_t)s1 * 160];

    // issue all gathers up front (max MLP)
    float v0b = __ldg(&yb0[128 + lane]);
    float v00 = __ldg(&yb0[0   + lane]);
    float v01 = __ldg(&yb0[32  + lane]);
    float v02 = __ldg(&yb0[64  + lane]);
    float v03 = __ldg(&yb0[96  + lane]);
    float v1b = __ldg(&yb1[128 + lane]);
    float v10 = __ldg(&yb1[0   + lane]);
    float v11 = __ldg(&yb1[32  + lane]);
    float v12 = __ldg(&yb1[64  + lane]);
    float v13 = __ldg(&yb1[96  + lane]);

    float m0 = v0b + a0.x * v00 + a0.y * v01 + a0.z * v02 + a0.w * v03;
    atomicAdd(&g_aggr[d0 * 32 + lane], m0);
    if (has1) {
        float m1 = v1b + a1.x * v10 + a1.y * v11 + a1.z * v12 + a1.w * v13;
        atomicAdd(&g_aggr[d1 * 32 + lane], m1);
    }
}

// ---------------- K_node: NNConv-root + fused GRU + next-round Y (or pooling) ----------------
// 8 warps, 8 nodes/warp. mh[n][0..31]=m (later hn), mh[n][32..63]=h
__global__ __launch_bounds__(256, 2) void k_node(const float* __restrict__ conv_b, // [32]
                                                 const float* __restrict__ bi,     // [96]
                                                 const float* __restrict__ bh,     // [96]
                                                 const int* __restrict__ batch,
                                                 int last) {
    __shared__ __align__(16) float mh[8][8][64];
    int t = threadIdx.x, wrp = t >> 5, lane = t & 31;
    int n0 = blockIdx.x * 64 + wrp * 8;
    float (*row)[64] = mh[wrp];

    // stage h
#pragma unroll
    for (int n = 0; n < 8; n++) {
        int node = n0 + n;
        row[n][32 + lane] = (node < NN) ? g_h[node * 32 + lane] : 0.0f;
    }
    __syncwarp();

    // --- root mat-vec ---
    ull acc[8];
#pragma unroll
    for (int n = 0; n < 8; n++) acc[n] = 0ull;
#pragma unroll
    for (int i4 = 0; i4 < 8; i4++) {
        ulonglong2 wv = *(const ulonglong2*)&P_RW[(i4 * 32 + lane) * 4];
#pragma unroll
        for (int n = 0; n < 8; n++) {
            ulonglong2 h2 = *(const ulonglong2*)&row[n][32 + i4 * 4];
            acc[n] = ffma2(h2.x, wv.x, acc[n]);
            acc[n] = ffma2(h2.y, wv.y, acc[n]);
        }
    }
    float cb = __ldg(&conv_b[lane]);
#pragma unroll
    for (int n = 0; n < 8; n++) {
        int node = n0 + n;
        float a = 0.0f;
        if (node < NN) {
            a = g_aggr[node * 32 + lane];
            g_aggr[node * 32 + lane] = 0.0f;   // pre-zero for next round
        }
        row[n][lane] = fmaxf(psum(acc[n]) + a + cb, 0.0f);
    }
    __syncwarp();

    // --- fused GRU gates over 64-dim [m;h] ---
    ull A[8], B[8], C[8], D[8];
#pragma unroll
    for (int n = 0; n < 8; n++) { A[n] = B[n] = C[n] = D[n] = 0ull; }
#pragma unroll
    for (int d4 = 0; d4 < 16; d4++) {
        ulonglong2 wr = *(const ulonglong2*)&P_WG[((d4 * 3 + 0) * 32 + lane) * 4];
        ulonglong2 wz = *(const ulonglong2*)&P_WG[((d4 * 3 + 1) * 32 + lane) * 4];
        ulonglong2 wn = *(const ulonglong2*)&P_WG[((d4 * 3 + 2) * 32 + lane) * 4];
#pragma unroll
        for (int n = 0; n < 8; n++) {
            ulonglong2 v = *(const ulonglong2*)&row[n][d4 * 4];
            A[n] = ffma2(v.x, wr.x, A[n]);
            A[n] = ffma2(v.y, wr.y, A[n]);
            B[n] = ffma2(v.x, wz.x, B[n]);
            B[n] = ffma2(v.y, wz.y, B[n]);
            if (d4 < 8) {           // m-part -> inn
                C[n] = ffma2(v.x, wn.x, C[n]);
                C[n] = ffma2(v.y, wn.y, C[n]);
            } else {                // h-part -> hn
                D[n] = ffma2(v.x, wn.x, D[n]);
                D[n] = ffma2(v.y, wn.y, D[n]);
            }
        }
    }
    float bir = __ldg(&bi[lane]), biz = __ldg(&bi[lane + 32]), bin = __ldg(&bi[lane + 64]);
    float bhr = __ldg(&bh[lane]), bhz = __ldg(&bh[lane + 32]), bhn = __ldg(&bh[lane + 64]);

    float hn[8];
#pragma unroll
    for (int n = 0; n < 8; n++) {
        float h  = row[n][32 + lane];
        float ra = psum(A[n]) + bir + bhr;
        float za = psum(B[n]) + biz + bhz;
        float cn = psum(C[n]) + bin;
        float dn = psum(D[n]) + bhn;
        float r  = 1.0f / (1.0f + __expf(-ra));
        float z  = 1.0f / (1.0f + __expf(-za));
        float nv = tanhf(cn + r * dn);
        hn[n] = (1.0f - z) * nv + z * h;
    }

    if (last) {
#pragma unroll
        for (int n = 0; n < 8; n++) {
            int node = n0 + n;
            if (node >= NN) break;
            int bg = __ldg(&batch[node]);
            atomicAdd(&g_pool[bg * 32 + lane], hn[n]);
            if (lane == 0) atomicAdd(&g_cnt[bg], 1.0f);
        }
        return;
    }

    // --- fused Y for next round ---
#pragma unroll
    for (int n = 0; n < 8; n++) row[n][lane] = hn[n];
    __syncwarp();

    ull y[8][5];
#pragma unroll
    for (int n = 0; n < 8; n++)
#pragma unroll
        for (int j = 0; j < 5; j++) y[n][j] = 0ull;
#pragma unroll
    for (int i4 = 0; i4 < 8; i4++) {
        ulonglong2 mw[5];
#pragma unroll
        for (int j = 0; j < 5; j++)
            mw[j] = *(const ulonglong2*)&P_MS[((i4 * 5 + j) * 32 + lane) * 4];
#pragma unroll
        for (int n = 0; n < 8; n++) {
            ulonglong2 h2 = *(const ulonglong2*)&row[n][i4 * 4];
#pragma unroll
            for (int j = 0; j < 5; j++) {
                y[n][j] = ffma2(h2.x, mw[j].x, y[n][j]);
                y[n][j] = ffma2(h2.y, mw[j].y, y[n][j]);
            }
        }
    }
#pragma unroll
    for (int n = 0; n < 8; n++) {
        int node = n0 + n;
        if (node >= NN) break;
        g_h[node * 32 + lane] = hn[n];
        float* yb = &g_Y[(size_t)node * 160];
#pragma unroll
        for (int j = 0; j < 5; j++) yb[j * 32 + lane] = psum(y[n][j]);
    }
}

// ---------------- K_final: logits + log_softmax ----------------
__global__ void k_final(const float* __restrict__ w,   // [2,32]
                        const float* __restrict__ b,   // [2]
                        float* __restrict__ out) {     // [G,2]
    int g = blockIdx.x * blockDim.x + threadIdx.x;
    if (g >= GG) return;
    float inv = 1.0f / fmaxf(g_cnt[g], 1.0f);
    float l0 = b[0], l1 = b[1];
#pragma unroll
    for (int d = 0; d < DD; d++) {
        float p = g_pool[g * DD + d] * inv;
        l0 += p * w[d];
        l1 += p * w[DD + d];
    }
    float mx  = fmaxf(l0, l1);
    float lse = mx + logf(__expf(l0 - mx) + __expf(l1 - mx));
    out[g * 2 + 0] = l0 - lse;
    out[g * 2 + 1] = l1 - lse;
}

// ---------------- launch ----------------
extern "C" void kernel_launch(void* const* d_in, const int* in_sizes, int n_in,
                              void* d_out, int out_size) {
    const float* x        = (const float*)d_in[0];
    const float* edge_attr= (const float*)d_in[1];
    const float* lin0_w   = (const float*)d_in[2];
    const float* lin0_b   = (const float*)d_in[3];
    const float* nn_w     = (const float*)d_in[4];
    const float* nn_b     = (const float*)d_in[5];
    const float* root_w   = (const float*)d_in[6];
    const float* conv_b   = (const float*)d_in[7];
    const float* gru_wi   = (const float*)d_in[8];
    const float* gru_wh   = (const float*)d_in[9];
    const float* gru_bi   = (const float*)d_in[10];
    const float* gru_bh   = (const float*)d_in[11];
    const float* lin1_w   = (const float*)d_in[12];
    const float* lin1_b   = (const float*)d_in[13];
    const int*   edge_idx = (const int*)d_in[14];
    const int*   batch    = (const int*)d_in[15];
    float* out = (float*)d_out;

    const int TPB = 256;
    const int nodeBlocks = (NN + 63) / 64;                      // 782
    const int edgeWarpBlocks = ((EE + 1) / 2 * 32 + TPB - 1) / TPB;  // 6250
    const int packBlocks = (GG * DD + TPB - 1) / TPB;           // 256

    k_pack<<<packBlocks, TPB>>>(root_w, gru_wi, gru_wh, nn_w, nn_b);
    k_init<<<nodeBlocks, TPB>>>(x, lin0_w, lin0_b);

    for (int round = 0; round < 3; round++) {
        k_edge<<<edgeWarpBlocks, TPB>>>(edge_idx, edge_attr);
        k_node<<<nodeBlocks, TPB>>>(conv_b, gru_bi, gru_bh, batch, round == 2);
    }

    k_final<<<(GG + TPB - 1) / TPB, TPB>>>(lin1_w, lin1_b, out);
}

// round 6
// speedup vs baseline: 1.2404x; 1.0002x over previous
#include <cuda_runtime.h>
#include <math.h>

#define NN   50000
#define EE   100000
#define GG   2048
#define DD   32

typedef unsigned long long ull;

// ---------------- device scratch ----------------
__device__ float g_h[NN * DD];
__device__ float g_aggr[NN * DD];
__device__ float g_Y[NN * 5 * DD];
__device__ float g_pool[GG * DD];
__device__ float g_cnt[GG];

// packed weights (16B chunks of 4 input-dims)
__device__ __align__(16) float P_RW[1024];   // root_w: [(i4*32+o)*4 + (i&3)]
__device__ __align__(16) float P_WG[6144];   // fused GRU: [((d4*3+g)*32+lane)*4 + (d&3)]
__device__ __align__(16) float P_MS[5120];   // 5 msg mats: [((i4*5+j)*32+lane)*4 + (i&3)]

// ---------------- f32x2 helpers ----------------
__device__ __forceinline__ ull ffma2(ull a, ull b, ull c) {
    ull d;
    asm("fma.rn.f32x2 %0, %1, %2, %3;" : "=l"(d) : "l"(a), "l"(b), "l"(c));
    return d;
}
__device__ __forceinline__ float flo(ull v) { return __uint_as_float((unsigned)v); }
__device__ __forceinline__ float fhi(ull v) { return __uint_as_float((unsigned)(v >> 32)); }
__device__ __forceinline__ float psum(ull v) { return flo(v) + fhi(v); }

// ---------------- K_pack: zero pool + build packed weights ----------------
__global__ void k_pack(const float* __restrict__ root_w,
                       const float* __restrict__ wi,
                       const float* __restrict__ wh,
                       const float* __restrict__ nn_w,
                       const float* __restrict__ nn_b) {
    int gid = blockIdx.x * blockDim.x + threadIdx.x;
    if (gid < GG * DD) g_pool[gid] = 0.0f;
    if (gid < GG) g_cnt[gid] = 0.0f;

    if (gid < 1024) {                        // root_w [i*32+o] -> P_RW
        int pos = gid & 3, o = (gid >> 2) & 31, i4 = gid >> 7;
        P_RW[gid] = root_w[(i4 * 4 + pos) * 32 + o];
    } else if (gid < 1024 + 6144) {          // fused GRU weights
        int t2 = gid - 1024;
        int pos = t2 & 3;
        int tmp = t2 >> 2;
        int lane = tmp & 31;
        int gk = (tmp >> 5) % 3;
        int d4 = (tmp >> 5) / 3;
        int d = d4 * 4 + pos;
        int k = gk * 32 + lane;
        P_WG[t2] = (d < 32) ? wi[k * 32 + d] : wh[k * 32 + (d - 32)];
    } else if (gid < 7168 + 5120) {          // 5 message matrices
        int t2 = gid - 7168;
        int pos = t2 & 3;
        int tmp = t2 >> 2;
        int lane = tmp & 31;
        int j = (tmp >> 5) % 5;
        int i4 = (tmp >> 5) / 5;
        int i = i4 * 4 + pos;
        P_MS[t2] = (j < 4) ? nn_w[(i * 32 + lane) * 4 + j] : nn_b[i * 32 + lane];
    }
}

// ---------------- K_init: h0 = relu(lin0); Y0 = h0 @ M_j ; zero aggr ----------------
// 8 warps, 8 nodes/warp -> 64 nodes/block
__global__ __launch_bounds__(256, 2) void k_init(const float* __restrict__ x,
                                                 const float* __restrict__ w,   // [32,11]
                                                 const float* __restrict__ b) { // [32]
    __shared__ __align__(16) float hsm[8][8][32];
    int t = threadIdx.x, wrp = t >> 5, lane = t & 31;
    int n0 = blockIdx.x * 64 + wrp * 8;
    float (*row)[32] = hsm[wrp];

    float bias = __ldg(&b[lane]);
    float wv[11];
#pragma unroll
    for (int f = 0; f < 11; f++) wv[f] = __ldg(&w[lane * 11 + f]);

    float hn[8];
#pragma unroll
    for (int n = 0; n < 8; n++) {
        int node = n0 + n;
        float s = bias;
        if (node < NN) {
#pragma unroll
            for (int f = 0; f < 11; f++) s += __ldg(&x[node * 11 + f]) * wv[f];
        }
        hn[n] = fmaxf(s, 0.0f);
        row[n][lane] = hn[n];
    }
    __syncwarp();

    ull y[8][5];
#pragma unroll
    for (int n = 0; n < 8; n++)
#pragma unroll
        for (int j = 0; j < 5; j++) y[n][j] = 0ull;

#pragma unroll
    for (int i4 = 0; i4 < 8; i4++) {
        ulonglong2 mw[5];
#pragma unroll
        for (int j = 0; j < 5; j++)
            mw[j] = *(const ulonglong2*)&P_MS[((i4 * 5 + j) * 32 + lane) * 4];
#pragma unroll
        for (int n = 0; n < 8; n++) {
            ulonglong2 h2 = *(const ulonglong2*)&row[n][i4 * 4];
#pragma unroll
            for (int j = 0; j < 5; j++) {
                y[n][j] = ffma2(h2.x, mw[j].x, y[n][j]);
                y[n][j] = ffma2(h2.y, mw[j].y, y[n][j]);
            }
        }
    }
#pragma unroll
    for (int n = 0; n < 8; n++) {
        int node = n0 + n;
        if (node >= NN) break;
        g_h[node * 32 + lane] = hn[n];
        g_aggr[node * 32 + lane] = 0.0f;
        float* yb = &g_Y[(size_t)node * 160];
#pragma unroll
        for (int j = 0; j < 5; j++) yb[j * 32 + lane] = psum(y[n][j]);
    }
}

// ---------------- K_edge: 2 edges per warp, batched gathers + scatter-add ----------------
__global__ void k_edge(const int* __restrict__ ei,        // [2,E]
                       const float* __restrict__ ea) {    // [E,4]
    int gt   = blockIdx.x * blockDim.x + threadIdx.x;
    int wrp  = gt >> 5;
    int lane = gt & 31;
    int e0   = wrp * 2;
    if (e0 >= EE) return;

    int s0 = __ldg(&ei[e0]);
    int d0 = __ldg(&ei[EE + e0]);
    float4 a0 = __ldg(&reinterpret_cast<const float4*>(ea)[e0]);
    const float* yb0 = &g_Y[(size_t)s0 * 160];

    bool has1 = (e0 + 1) < EE;
    int s1 = has1 ? __ldg(&ei[e0 + 1]) : s0;
    int d1 = has1 ? __ldg(&ei[EE + e0 + 1]) : d0;
    float4 a1 = has1 ? __ldg(&reinterpret_cast<const float4*>(ea)[e0 + 1]) : a0;
    const float* yb1 = &g_Y[(size_t)s1 * 160];

    float v0b = __ldg(&yb0[128 + lane]);
    float v00 = __ldg(&yb0[0   + lane]);
    float v01 = __ldg(&yb0[32  + lane]);
    float v02 = __ldg(&yb0[64  + lane]);
    float v03 = __ldg(&yb0[96  + lane]);
    float v1b = __ldg(&yb1[128 + lane]);
    float v10 = __ldg(&yb1[0   + lane]);
    float v11 = __ldg(&yb1[32  + lane]);
    float v12 = __ldg(&yb1[64  + lane]);
    float v13 = __ldg(&yb1[96  + lane]);

    float m0 = v0b + a0.x * v00 + a0.y * v01 + a0.z * v02 + a0.w * v03;
    atomicAdd(&g_aggr[d0 * 32 + lane], m0);
    if (has1) {
        float m1 = v1b + a1.x * v10 + a1.y * v11 + a1.z * v12 + a1.w * v13;
        atomicAdd(&g_aggr[d1 * 32 + lane], m1);
    }
}

// ---------------- K_node: NNConv-root + fused GRU + next-round Y (or pooling) ----------------
// 8 warps, 4 nodes/warp -> 32 nodes/block; 3 blocks/SM for latency coverage.
__global__ __launch_bounds__(256, 3) void k_node(const float* __restrict__ conv_b, // [32]
                                                 const float* __restrict__ bi,     // [96]
                                                 const float* __restrict__ bh,     // [96]
                                                 const int* __restrict__ batch,
                                                 int last) {
    __shared__ __align__(16) float mh[8][4][64];
    int t = threadIdx.x, wrp = t >> 5, lane = t & 31;
    int n0 = blockIdx.x * 32 + wrp * 4;
    float (*row)[64] = mh[wrp];

    // stage h
#pragma unroll
    for (int n = 0; n < 4; n++) {
        int node = n0 + n;
        row[n][32 + lane] = (node < NN) ? g_h[node * 32 + lane] : 0.0f;
    }
    __syncwarp();

    // --- root mat-vec ---
    ull acc[4];
#pragma unroll
    for (int n = 0; n < 4; n++) acc[n] = 0ull;
#pragma unroll
    for (int i4 = 0; i4 < 8; i4++) {
        ulonglong2 wv = *(const ulonglong2*)&P_RW[(i4 * 32 + lane) * 4];
#pragma unroll
        for (int n = 0; n < 4; n++) {
            ulonglong2 h2 = *(const ulonglong2*)&row[n][32 + i4 * 4];
            acc[n] = ffma2(h2.x, wv.x, acc[n]);
            acc[n] = ffma2(h2.y, wv.y, acc[n]);
        }
    }
    float cb = __ldg(&conv_b[lane]);
#pragma unroll
    for (int n = 0; n < 4; n++) {
        int node = n0 + n;
        float a = 0.0f;
        if (node < NN) {
            a = g_aggr[node * 32 + lane];
            g_aggr[node * 32 + lane] = 0.0f;   // pre-zero for next round
        }
        row[n][lane] = fmaxf(psum(acc[n]) + a + cb, 0.0f);
    }
    __syncwarp();

    // --- fused GRU gates over 64-dim [m;h] ---
    ull A[4], B[4], C[4], D[4];
#pragma unroll
    for (int n = 0; n < 4; n++) { A[n] = B[n] = C[n] = D[n] = 0ull; }
#pragma unroll
    for (int d4 = 0; d4 < 16; d4++) {
        ulonglong2 wr = *(const ulonglong2*)&P_WG[((d4 * 3 + 0) * 32 + lane) * 4];
        ulonglong2 wz = *(const ulonglong2*)&P_WG[((d4 * 3 + 1) * 32 + lane) * 4];
        ulonglong2 wn = *(const ulonglong2*)&P_WG[((d4 * 3 + 2) * 32 + lane) * 4];
#pragma unroll
        for (int n = 0; n < 4; n++) {
            ulonglong2 v = *(const ulonglong2*)&row[n][d4 * 4];
            A[n] = ffma2(v.x, wr.x, A[n]);
            A[n] = ffma2(v.y, wr.y, A[n]);
            B[n] = ffma2(v.x, wz.x, B[n]);
            B[n] = ffma2(v.y, wz.y, B[n]);
            if (d4 < 8) {           // m-part -> inn
                C[n] = ffma2(v.x, wn.x, C[n]);
                C[n] = ffma2(v.y, wn.y, C[n]);
            } else {                // h-part -> hn
                D[n] = ffma2(v.x, wn.x, D[n]);
                D[n] = ffma2(v.y, wn.y, D[n]);
            }
        }
    }
    float bir = __ldg(&bi[lane]), biz = __ldg(&bi[lane + 32]), bin = __ldg(&bi[lane + 64]);
    float bhr = __ldg(&bh[lane]), bhz = __ldg(&bh[lane + 32]), bhn = __ldg(&bh[lane + 64]);

    float hn[4];
#pragma unroll
    for (int n = 0; n < 4; n++) {
        float h  = row[n][32 + lane];
        float ra = psum(A[n]) + bir + bhr;
        float za = psum(B[n]) + biz + bhz;
        float cn = psum(C[n]) + bin;
        float dn = psum(D[n]) + bhn;
        float r  = 1.0f / (1.0f + __expf(-ra));
        float z  = 1.0f / (1.0f + __expf(-za));
        float nv = tanhf(cn + r * dn);
        hn[n] = (1.0f - z) * nv + z * h;
    }

    if (last) {
#pragma unroll
        for (int n = 0; n < 4; n++) {
            int node = n0 + n;
            if (node >= NN) break;
            int bg = __ldg(&batch[node]);
            atomicAdd(&g_pool[bg * 32 + lane], hn[n]);
            if (lane == 0) atomicAdd(&g_cnt[bg], 1.0f);
        }
        return;
    }

    // --- fused Y for next round ---
#pragma unroll
    for (int n = 0; n < 4; n++) row[n][lane] = hn[n];
    __syncwarp();

    ull y[4][5];
#pragma unroll
    for (int n = 0; n < 4; n++)
#pragma unroll
        for (int j = 0; j < 5; j++) y[n][j] = 0ull;
#pragma unroll
    for (int i4 = 0; i4 < 8; i4++) {
        ulonglong2 mw[5];
#pragma unroll
        for (int j = 0; j < 5; j++)
            mw[j] = *(const ulonglong2*)&P_MS[((i4 * 5 + j) * 32 + lane) * 4];
#pragma unroll
        for (int n = 0; n < 4; n++) {
            ulonglong2 h2 = *(const ulonglong2*)&row[n][i4 * 4];
#pragma unroll
            for (int j = 0; j < 5; j++) {
                y[n][j] = ffma2(h2.x, mw[j].x, y[n][j]);
                y[n][j] = ffma2(h2.y, mw[j].y, y[n][j]);
            }
        }
    }
#pragma unroll
    for (int n = 0; n < 4; n++) {
        int node = n0 + n;
        if (node >= NN) break;
        g_h[node * 32 + lane] = hn[n];
        float* yb = &g_Y[(size_t)node * 160];
#pragma unroll
        for (int j = 0; j < 5; j++) yb[j * 32 + lane] = psum(y[n][j]);
    }
}

// ---------------- K_final: logits + log_softmax ----------------
__global__ void k_final(const float* __restrict__ w,   // [2,32]
                        const float* __restrict__ b,   // [2]
                        float* __restrict__ out) {     // [G,2]
    int g = blockIdx.x * blockDim.x + threadIdx.x;
    if (g >= GG) return;
    float inv = 1.0f / fmaxf(g_cnt[g], 1.0f);
    float l0 = b[0], l1 = b[1];
#pragma unroll
    for (int d = 0; d < DD; d++) {
        float p = g_pool[g * DD + d] * inv;
        l0 += p * w[d];
        l1 += p * w[DD + d];
    }
    float mx  = fmaxf(l0, l1);
    float lse = mx + logf(__expf(l0 - mx) + __expf(l1 - mx));
    out[g * 2 + 0] = l0 - lse;
    out[g * 2 + 1] = l1 - lse;
}

// ---------------- launch ----------------
extern "C" void kernel_launch(void* const* d_in, const int* in_sizes, int n_in,
                              void* d_out, int out_size) {
    const float* x        = (const float*)d_in[0];
    const float* edge_attr= (const float*)d_in[1];
    const float* lin0_w   = (const float*)d_in[2];
    const float* lin0_b   = (const float*)d_in[3];
    const float* nn_w     = (const float*)d_in[4];
    const float* nn_b     = (const float*)d_in[5];
    const float* root_w   = (const float*)d_in[6];
    const float* conv_b   = (const float*)d_in[7];
    const float* gru_wi   = (const float*)d_in[8];
    const float* gru_wh   = (const float*)d_in[9];
    const float* gru_bi   = (const float*)d_in[10];
    const float* gru_bh   = (const float*)d_in[11];
    const float* lin1_w   = (const float*)d_in[12];
    const float* lin1_b   = (const float*)d_in[13];
    const int*   edge_idx = (const int*)d_in[14];
    const int*   batch    = (const int*)d_in[15];
    float* out = (float*)d_out;

    const int TPB = 256;
    const int initBlocks = (NN + 63) / 64;                      // 782
    const int nodeBlocks = (NN + 31) / 32;                      // 1563
    const int edgeWarpBlocks = ((EE + 1) / 2 * 32 + TPB - 1) / TPB;  // 6250
    const int packBlocks = (GG * DD + TPB - 1) / TPB;           // 256

    k_pack<<<packBlocks, TPB>>>(root_w, gru_wi, gru_wh, nn_w, nn_b);
    k_init<<<initBlocks, TPB>>>(x, lin0_w, lin0_b);

    for (int round = 0; round < 3; round++) {
        k_edge<<<edgeWarpBlocks, TPB>>>(edge_idx, edge_attr);
        k_node<<<nodeBlocks, TPB>>>(conv_b, gru_bi, gru_bh, batch, round == 2);
    }

    k_final<<<(GG + TPB - 1) / TPB, TPB>>>(lin1_w, lin1_b, out);
}